// round 11
// baseline (speedup 1.0000x reference)
#include <cuda_runtime.h>

// ---------------------------------------------------------------------------
// Photonic Clements mesh, N=128. One warp per column; lane t owns rows
// 8t..8t+7 as v0..v7. Round-10 structure (shfl hoist, 3-slot rotation,
// predicate-free corners, pointer-strided loads, peeled tail) plus:
//  - ROUND 11a: prefetch.global.L1 on each slot's next reload address
//    (issued ~3 iterations ahead) -> table LDGs become L1 hits instead of
//    exposed ~250-cycle L2 round trips.
//  - ROUND 11b: __sincosf in the phase kernel (fast path, ~1e-6 abs err on
//    [0,2pi) -- negligible vs the 1e-3 threshold).
// Output serialization identical to rounds 4-10 (mode on out_size).
// ---------------------------------------------------------------------------

#define NCOLS   128
#define NLAYERS 255
#define FULL    0xffffffffu

#define AM_  0.97467943448089633f    // sqrt(1-0.05)
#define PP_  0.71063352017759484f    // sqrt(0.5+0.005)
#define QQ_  0.70356236397351441f    // sqrt(0.5-0.005)
#define AMP_ (AM_*PP_)
#define AMQ_ (AM_*QQ_)
#define AX_  0.98994949366116653f    // sqrt(1-0.02)
#define XC_  (AX_*0.1f)                       // aX*sqrt(CT)
#define XS_  (AX_*0.99498743710661995f)       // aX*sqrt(1-CT), corner scalar

// phase table: layer k, lane t reads float4s [k*64 + 2t] and [k*64 + 2t + 1]
// +512 float4 (8 KB) padding so tail prefetches stay inside the allocation.
__device__ float4 g_phase4[NLAYERS * 64 + 512];

__global__ void phase_kernel(const float* __restrict__ theta_even) {
    int i = blockIdx.x * blockDim.x + threadIdx.x;
    if (i < NLAYERS * NCOLS) {
        float s, c;
        __sincosf(theta_even[i], &s, &c);   // fast path; inputs in [0, 2pi)
        reinterpret_cast<float2*>(g_phase4)[i] = make_float2(c, s);
    }
}

// v *= (c + i s)
#define CMUL(v, c_, s_) do { \
    float _nx = fmaf((v).x, (c_), -(v).y * (s_)); \
    float _ny = fmaf((v).x, (s_),  (v).y * (c_)); \
    (v).x = _nx; (v).y = _ny; } while (0)

// [a;b] <- [[A,iB],[iB,A]][a;b]
#define MIX(a, b, A, B) do { \
    float _ar = fmaf((A), (a).x, -(B) * (b).y); \
    float _ai = fmaf((A), (a).y,  (B) * (b).x); \
    float _br = fmaf((A), (b).x, -(B) * (a).y); \
    float _bi = fmaf((A), (b).y,  (B) * (a).x); \
    (a).x = _ar; (a).y = _ai; (b).x = _br; (b).y = _bi; } while (0)

// L1 prefetch of the cache lines this lane's next reload will touch
#define PF(p) do { \
    asm volatile("prefetch.global.L1 [%0];"      :: "l"(p)); \
    asm volatile("prefetch.global.L1 [%0+1024];" :: "l"(p)); } while (0)

// One iteration: D(a), M, D(b), M, X. Boundary pairs first; shuffles overlap
// the middle-pair math. Corners folded into per-lane coeffs cA/cB.
#define ITER(A0, A1, B0, B1) do { \
    CMUL(v0, (A0).x, (A0).y); \
    CMUL(v6, (A1).z, (A1).w); \
    MIX(v0, v1, AMP_, AMQ_); \
    MIX(v6, v7, AMP_, AMQ_); \
    CMUL(v0, (B0).x, (B0).y); \
    CMUL(v6, (B1).z, (B1).w); \
    MIX(v0, v1, AMP_, AMQ_); \
    MIX(v6, v7, AMP_, AMQ_); \
    float _nb0x = __shfl_down_sync(FULL, v0.x, 1);   /* lane t+1's v0 = row 8t+8 */ \
    float _nb0y = __shfl_down_sync(FULL, v0.y, 1); \
    float _nb7x = __shfl_up_sync  (FULL, v7.x, 1);   /* lane t-1's v7 = row 8t-1 */ \
    float _nb7y = __shfl_up_sync  (FULL, v7.y, 1); \
    CMUL(v2, (A0).z, (A0).w); \
    CMUL(v4, (A1).x, (A1).y); \
    MIX(v2, v3, AMP_, AMQ_); \
    MIX(v4, v5, AMP_, AMQ_); \
    CMUL(v2, (B0).z, (B0).w); \
    CMUL(v4, (B1).x, (B1).y); \
    MIX(v2, v3, AMP_, AMQ_); \
    MIX(v4, v5, AMP_, AMQ_); \
    MIX(v1, v2, XC_, XS_); \
    MIX(v3, v4, XC_, XS_); \
    MIX(v5, v6, XC_, XS_); \
    float _n7x = fmaf(cA7, v7.x, -cB7 * _nb0y); \
    float _n7y = fmaf(cA7, v7.y,  cB7 * _nb0x); \
    float _n0x = fmaf(cA0, v0.x, -cB0 * _nb7y); \
    float _n0y = fmaf(cA0, v0.y,  cB0 * _nb7x); \
    v7.x = _n7x; v7.y = _n7y; \
    v0.x = _n0x; v0.y = _n0y; } while (0)

// reload a slot from pointer p: [0],[1] = layer 2jn+1; [64],[65] = layer 2jn+2
#define LDP(S0, S1, S2, S3, p) do { \
    (S0) = (p)[0]; (S1) = (p)[1]; (S2) = (p)[64]; (S3) = (p)[65]; } while (0)

__global__ void __launch_bounds__(32, 1)
mesh_kernel(const float* __restrict__ theta_in,
            const float* __restrict__ theta_out,
            float* __restrict__ out,
            int mode)   // 1 = real-only (16384 floats), 2 = planar (32768 floats)
{
    const int c = blockIdx.x;    // column (input port)
    const int t = threadIdx.x;   // lane: rows 8t..8t+7

    // per-lane boundary coefficients (corners folded in)
    const float cA7 = (t < 31) ? XC_ : XS_;
    const float cB7 = (t < 31) ? XS_ : 0.f;
    const float cA0 = (t > 0)  ? XC_ : XS_;
    const float cB0 = (t > 0)  ? XS_ : 0.f;

    float2 v0 = {0.f, 0.f}, v1 = {0.f, 0.f}, v2 = {0.f, 0.f}, v3 = {0.f, 0.f};
    float2 v4 = {0.f, 0.f}, v5 = {0.f, 0.f}, v6 = {0.f, 0.f}, v7 = {0.f, 0.f};

    // --- input: rows 2c, 2c+1 of column c of MMI_IN @ diag(e^{i th_in}) ---
    {
        float s, co;
        sincosf(theta_in[c], &s, &co);
        float2 ain = make_float2( AMP_ * co, AMP_ * s);   //  aM*p * e^{i th}
        float2 bin = make_float2(-AMQ_ * s,  AMQ_ * co);  // i*aM*q * e^{i th}
        int slot = 2 * c - 8 * t;
        if      (slot == 0) { v0 = ain; v1 = bin; }
        else if (slot == 2) { v2 = ain; v3 = bin; }
        else if (slot == 4) { v4 = ain; v5 = bin; }
        else if (slot == 6) { v6 = ain; v7 = bin; }
    }

    const float4* base = g_phase4 + 2 * t;

    // --- first: D0, M, X (hoisted form) ---
    {
        float4 p01 = base[0], p23 = base[1];
        CMUL(v0, p01.x, p01.y);
        CMUL(v6, p23.z, p23.w);
        MIX(v0, v1, AMP_, AMQ_);
        MIX(v6, v7, AMP_, AMQ_);
        float nb0x = __shfl_down_sync(FULL, v0.x, 1);
        float nb0y = __shfl_down_sync(FULL, v0.y, 1);
        float nb7x = __shfl_up_sync  (FULL, v7.x, 1);
        float nb7y = __shfl_up_sync  (FULL, v7.y, 1);
        CMUL(v2, p01.z, p01.w);
        CMUL(v4, p23.x, p23.y);
        MIX(v2, v3, AMP_, AMQ_);
        MIX(v4, v5, AMP_, AMQ_);
        MIX(v1, v2, XC_, XS_);
        MIX(v3, v4, XC_, XS_);
        MIX(v5, v6, XC_, XS_);
        float n7x = fmaf(cA7, v7.x, -cB7 * nb0y);
        float n7y = fmaf(cA7, v7.y,  cB7 * nb0x);
        float n0x = fmaf(cA0, v0.x, -cB0 * nb7y);
        float n0y = fmaf(cA0, v0.y,  cB0 * nb7x);
        v7.x = n7x; v7.y = n7y;
        v0.x = n0x; v0.y = n0y;
    }

    // iteration j (0..125) consumes layers 2j+1, 2j+2; tail = D253, M, D254.
    // 3 rotating slots; per-slot pointers advance 6 layers (384 float4s) per
    // reload. After each pointer advance, prefetch the NEXT reload's lines
    // into L1 (~3 iterations of lead time).
    float4 s0a0, s0a1, s0b0, s0b1;
    float4 s1a0, s1a1, s1b0, s1b1;
    float4 s2a0, s2a1, s2b0, s2b1;
    LDP(s0a0, s0a1, s0b0, s0b1, base + 1 * 64);   // layers 1,2
    LDP(s1a0, s1a1, s1b0, s1b1, base + 3 * 64);   // layers 3,4
    LDP(s2a0, s2a1, s2b0, s2b1, base + 5 * 64);   // layers 5,6

    const float4* p0 = base + 7 * 64;    // jn=3  -> layer 7
    const float4* p1 = base + 9 * 64;    // jn=4  -> layer 9
    const float4* p2 = base + 11 * 64;   // jn=5  -> layer 11
    PF(p0); PF(p1); PF(p2);

    // 41 full trips: j = 0,3,...,120 (iters 0..122; reloads jn up to 125)
#pragma unroll 1
    for (int m = 0; m < 41; m++) {
        ITER(s0a0, s0a1, s0b0, s0b1);
        LDP(s0a0, s0a1, s0b0, s0b1, p0);
        p0 += 384; PF(p0);
        ITER(s1a0, s1a1, s1b0, s1b1);
        LDP(s1a0, s1a1, s1b0, s1b1, p1);
        p1 += 384; PF(p1);
        ITER(s2a0, s2a1, s2b0, s2b1);
        LDP(s2a0, s2a1, s2b0, s2b1, p2);
        p2 += 384; PF(p2);
    }

    // peeled final trip: iters 123,124,125; reload slot0 with layers 253,254
    // (p0 now points at jn=126 -> layer 253)
    ITER(s0a0, s0a1, s0b0, s0b1);
    LDP(s0a0, s0a1, s0b0, s0b1, p0);
    ITER(s1a0, s1a1, s1b0, s1b1);
    ITER(s2a0, s2a1, s2b0, s2b1);

    // --- tail: D253, M, D254 (slot 0 holds layers 253/254) ---
    CMUL(v0, s0a0.x, s0a0.y);
    CMUL(v2, s0a0.z, s0a0.w);
    CMUL(v4, s0a1.x, s0a1.y);
    CMUL(v6, s0a1.z, s0a1.w);
    MIX(v0, v1, AMP_, AMQ_);
    MIX(v2, v3, AMP_, AMQ_);
    MIX(v4, v5, AMP_, AMQ_);
    MIX(v6, v7, AMP_, AMQ_);
    CMUL(v0, s0b0.x, s0b0.y);
    CMUL(v2, s0b0.z, s0b0.w);
    CMUL(v4, s0b1.x, s0b1.y);
    CMUL(v6, s0b1.z, s0b1.w);

    // --- output rows jj = 4t..4t+3: MMI_OUT pair reduce, then e^{i th_out} ---
#define OUTP(va, vb, jj) do { \
        float _ox = fmaf(AMP_, (va).x, -AMQ_ * (vb).y); \
        float _oy = fmaf(AMP_, (va).y,  AMQ_ * (vb).x); \
        float _so, _co; sincosf(theta_out[jj], &_so, &_co); \
        float _re = _ox * _co - _oy * _so; \
        float _im = _ox * _so + _oy * _co; \
        if (mode == 1) { out[(jj) * NCOLS + c] = _re; } \
        else { out[(jj) * NCOLS + c] = _re; \
               out[NCOLS * NCOLS + (jj) * NCOLS + c] = _im; } } while (0)

    OUTP(v0, v1, 4 * t);
    OUTP(v2, v3, 4 * t + 1);
    OUTP(v4, v5, 4 * t + 2);
    OUTP(v6, v7, 4 * t + 3);
#undef OUTP
}

extern "C" void kernel_launch(void* const* d_in, const int* in_sizes, int n_in,
                              void* d_out, int out_size) {
    // Inputs identified by SIZE (theta_even = unique 32640-elem array;
    // theta_in precedes theta_out).
    const float* th_ev  = nullptr;
    const float* small_[2] = {nullptr, nullptr};
    int ns = 0;
    for (int i = 0; i < n_in && i < 3; i++) {
        if (in_sizes[i] > 1000) th_ev = (const float*)d_in[i];
        else if (ns < 2)        small_[ns++] = (const float*)d_in[i];
    }
    const float* th_in  = small_[0];
    const float* th_out = small_[1];

    int mode = (out_size == NCOLS * NCOLS) ? 1 : 2;  // 16384 -> real-only, else planar

    phase_kernel<<<(NLAYERS * NCOLS + 255) / 256, 256>>>(th_ev);
    mesh_kernel<<<NCOLS, 32>>>(th_in, th_out, (float*)d_out, mode);
}